// round 16
// baseline (speedup 1.0000x reference)
#include <cuda_runtime.h>
#include <cuda_fp16.h>
#include <cstdint>

#define NV 50000
#define NE 1250000
#define DD 64

// ---------------- scratch (device globals: no runtime allocation allowed) ----
__device__ __half g_h[(size_t)NV * DD];        // node projection h = nf@Wn + bn (fp16)
__device__ __half g_msg[(size_t)NE * DD];      // messages, dst-sorted (CSR) order
__device__ int    g_rank[NE];                  // rank of edge within its dst bucket
__device__ int    g_cnt[NV];                   // histogram (zero at entry; cleared in scan1)
__device__ int    g_off[NV + 1];               // CSR offsets
__device__ int    g_bsum[64];                  // scan block sums

// ---------------- helpers ---------------------------------------------------
__device__ __forceinline__ float sspf(float x) {
    // shifted softplus via fast-math MUFU: log(1+e^x) - log(2)
    return fmaxf(x, 0.f) + __logf(1.f + __expf(-fabsf(x))) - 0.69314718055994531f;
}

// fp16 mma m16n8k16, fp32 accumulate
__device__ __forceinline__ void mma_f16(float c[4], unsigned a0, unsigned a1,
                                        unsigned a2, unsigned a3,
                                        unsigned b0, unsigned b1) {
    asm("mma.sync.aligned.m16n8k16.row.col.f32.f16.f16.f32 "
        "{%0,%1,%2,%3}, {%4,%5,%6,%7}, {%8,%9}, {%0,%1,%2,%3};"
        : "+f"(c[0]), "+f"(c[1]), "+f"(c[2]), "+f"(c[3])
        : "r"(a0), "r"(a1), "r"(a2), "r"(a3), "r"(b0), "r"(b1));
}

// Pack 64x64 row-major W into per-lane m16n8k16 B-fragment order (fp16).
__device__ __forceinline__ void packW(const float* __restrict__ W, unsigned* Wp,
                                      int tid, int nthr) {
    for (int idx = tid; idx < 2048; idx += nthr) {
        int j    = idx & 1;
        int lane = (idx >> 1) & 31;
        int nt   = (idx >> 6) & 7;
        int ks   = idx >> 9;                  // 0..3
        int g = lane >> 2, t4 = lane & 3;
        int kb = ks * 16 + t4 * 2 + j * 8;
        int n  = nt * 8 + g;
        __half2 v = __floats2half2_rn(W[kb * DD + n], W[(kb + 1) * DD + n]);
        Wp[idx] = *(unsigned*)&v;
    }
}

// [128,64] @ [64,64] (h_kernel): A fp16 in smem, W pre-packed fragments.
__device__ __forceinline__ void gemm_tile(const __half (*As)[72],
                                          const unsigned* __restrict__ Wp,
                                          float acc[8][4], int wr, int gid,
                                          int tig, int lane) {
    #pragma unroll
    for (int ks = 0; ks < 4; ks++) {
        int k0 = ks * 16 + tig * 2;
        unsigned a0 = *(const unsigned*)&As[wr + gid    ][k0];
        unsigned a1 = *(const unsigned*)&As[wr + gid + 8][k0];
        unsigned a2 = *(const unsigned*)&As[wr + gid    ][k0 + 8];
        unsigned a3 = *(const unsigned*)&As[wr + gid + 8][k0 + 8];
        #pragma unroll
        for (int nt = 0; nt < 8; nt++) {
            uint2 b = ((const uint2*)Wp)[(ks * 8 + nt) * 32 + lane];
            mma_f16(acc[nt], a0, a1, a2, a3, b.x, b.y);
        }
    }
}

// ---------------- CSR build (3-phase parallel scan) --------------------------
__global__ void hist_kernel(const int* __restrict__ dst) {
    int e = blockIdx.x * blockDim.x + threadIdx.x;
    if (e < NE) g_rank[e] = atomicAdd(&g_cnt[dst[e]], 1);
}
__global__ void scan1_kernel() {
    __shared__ int ws[32];
    int t = threadIdx.x, b = blockIdx.x;
    int i = b * 1024 + t;
    int x = 0;
    if (i < NV) {
        x = g_cnt[i];
        g_cnt[i] = 0;  // re-establish zero invariant for the next replay
    }
    int incl = x;
    #pragma unroll
    for (int o = 1; o < 32; o <<= 1) {
        int n = __shfl_up_sync(0xffffffffu, incl, o);
        if ((t & 31) >= o) incl += n;
    }
    if ((t & 31) == 31) ws[t >> 5] = incl;
    __syncthreads();
    if (t < 32) {
        int v = ws[t];
        int iv = v;
        #pragma unroll
        for (int o = 1; o < 32; o <<= 1) {
            int n = __shfl_up_sync(0xffffffffu, iv, o);
            if (t >= o) iv += n;
        }
        ws[t] = iv - v;  // exclusive warp prefix
    }
    __syncthreads();
    int excl = ws[t >> 5] + incl - x;
    if (i < NV) g_off[i] = excl;
    if (t == 1023) g_bsum[b] = excl + x;
}
__global__ void scan2_kernel() {
    int run = 0;
    const int nb = (NV + 1023) / 1024;
    for (int b = 0; b < nb; b++) {
        int v = g_bsum[b];
        g_bsum[b] = run;
        run += v;
    }
}
__global__ void scan3_kernel() {
    int t = threadIdx.x, b = blockIdx.x;
    int i = b * 1024 + t;
    if (i < NV) g_off[i] += g_bsum[b];
    if (i == 0) g_off[NV] = NE;
}

// ---------------- h = node_feats @ Wn + bn (fp16 output) ---------------------
struct HSmem {
    __half As[128][72];
    unsigned Wp[2048];
    float bs[64];
};
__global__ void __launch_bounds__(256, 2)
h_kernel(const float* __restrict__ nf, const float* __restrict__ Wn,
         const float* __restrict__ bn) {
    extern __shared__ char smraw[];
    HSmem& sm = *reinterpret_cast<HSmem*>(smraw);
    int tid = threadIdx.x, lane = tid & 31, warp = tid >> 5;
    int gid = lane >> 2, tig = lane & 3, wr = warp * 16;
    packW(Wn, sm.Wp, tid, 256);
    if (tid < 64) sm.bs[tid] = bn[tid];
    int base = blockIdx.x * 128;
    int rows = min(128, NV - base);
    #pragma unroll
    for (int j = 0; j < 8; j++) {
        int f4 = tid + j * 256;
        int r = f4 >> 4, c4 = f4 & 15;
        float4 v = (r < rows) ? ((const float4*)(nf + (size_t)(base + r) * DD))[c4]
                              : make_float4(0.f, 0.f, 0.f, 0.f);
        __half2 h0 = __floats2half2_rn(v.x, v.y);
        __half2 h1 = __floats2half2_rn(v.z, v.w);
        *(uint2*)&sm.As[r][c4 * 4] = make_uint2(*(unsigned*)&h0, *(unsigned*)&h1);
    }
    __syncthreads();
    float acc[8][4];
    #pragma unroll
    for (int i = 0; i < 8; i++)
        #pragma unroll
        for (int j = 0; j < 4; j++) acc[i][j] = 0.f;
    gemm_tile(sm.As, sm.Wp, acc, wr, gid, tig, lane);
    #pragma unroll
    for (int nt = 0; nt < 8; nt++) {
        int c0 = nt * 8 + tig * 2;
        float b0 = sm.bs[c0], b1 = sm.bs[c0 + 1];
        int r0 = wr + gid, r1 = wr + gid + 8;
        if (r0 < rows)
            *(__half2*)(g_h + (size_t)(base + r0) * DD + c0) =
                __floats2half2_rn(acc[nt][0] + b0, acc[nt][1] + b1);
        if (r1 < rows)
            *(__half2*)(g_h + (size_t)(base + r1) * DD + c0) =
                __floats2half2_rn(acc[nt][2] + b0, acc[nt][3] + b1);
    }
}

// ---------------- edge kernel: 32 rows/warp, B-fragments amortized ----------
struct EdgeSmem {
    __half As[256][72];    // fp16 edge tile / intermediate / fp16 msg staging
    unsigned Wp1[2048];
    unsigned Wp2[2048];
    float b1s[64], b2s[64];
    int slotS[256];
};
__global__ void __launch_bounds__(256, 2)
edge_kernel(const float* __restrict__ ef, const int* __restrict__ src,
            const int* __restrict__ dst, const float* __restrict__ We1,
            const float* __restrict__ be1, const float* __restrict__ We2,
            const float* __restrict__ be2) {
    extern __shared__ char smraw[];
    EdgeSmem& sm = *reinterpret_cast<EdgeSmem*>(smraw);
    const int tid = threadIdx.x, lane = tid & 31, warp = tid >> 5;
    const int gid = lane >> 2, tig = lane & 3, wr = warp * 32;
    // the four rows this thread owns (two 16-row mma sub-blocks)
    const int q0 = wr + gid, q1 = q0 + 8, q2 = q0 + 16, q3 = q0 + 24;

    packW(We1, sm.Wp1, tid, 256);
    packW(We2, sm.Wp2, tid, 256);
    if (tid < 64) { sm.b1s[tid] = be1[tid]; sm.b2s[tid] = be2[tid]; }

    const int numTiles = (NE + 255) / 256;  // 4883
    for (int tile = blockIdx.x; tile < numTiles; tile += gridDim.x) {
        const int base = tile * 256;
        const int rows = min(256, NE - base);
        __syncthreads();  // prev-iter readers done; Wp ready (first iter)

        if (tid < rows)
            sm.slotS[tid] = g_off[dst[base + tid]] + g_rank[base + tid];

        #pragma unroll
        for (int j = 0; j < 16; j++) {
            int f4 = tid + j * 256;
            int r = f4 >> 4, c4 = f4 & 15;
            float4 v = (r < rows)
                           ? ((const float4*)(ef + (size_t)(base + r) * DD))[c4]
                           : make_float4(0.f, 0.f, 0.f, 0.f);
            __half2 h0 = __floats2half2_rn(v.x, v.y);
            __half2 h1 = __floats2half2_rn(v.z, v.w);
            *(uint2*)&sm.As[r][c4 * 4] = make_uint2(*(unsigned*)&h0, *(unsigned*)&h1);
        }
        __syncthreads();

        // ---- GEMM1: 32 rows/warp, B loaded once per (ks,nt) ----
        float acc[16][4];  // [sub*8 + nt]
        #pragma unroll
        for (int i = 0; i < 16; i++)
            #pragma unroll
            for (int j = 0; j < 4; j++) acc[i][j] = 0.f;
        #pragma unroll
        for (int ks = 0; ks < 4; ks++) {
            int k0 = ks * 16 + tig * 2;
            unsigned a0 = *(const unsigned*)&sm.As[q0][k0];
            unsigned a1 = *(const unsigned*)&sm.As[q1][k0];
            unsigned a2 = *(const unsigned*)&sm.As[q0][k0 + 8];
            unsigned a3 = *(const unsigned*)&sm.As[q1][k0 + 8];
            unsigned a4 = *(const unsigned*)&sm.As[q2][k0];
            unsigned a5 = *(const unsigned*)&sm.As[q3][k0];
            unsigned a6 = *(const unsigned*)&sm.As[q2][k0 + 8];
            unsigned a7 = *(const unsigned*)&sm.As[q3][k0 + 8];
            #pragma unroll
            for (int nt = 0; nt < 8; nt++) {
                uint2 b = ((const uint2*)sm.Wp1)[(ks * 8 + nt) * 32 + lane];
                mma_f16(acc[nt],     a0, a1, a2, a3, b.x, b.y);
                mma_f16(acc[8 + nt], a4, a5, a6, a7, b.x, b.y);
            }
        }
        __syncthreads();

        // ssp(x + b1) -> back into As (fp16)
        #pragma unroll
        for (int nt = 0; nt < 8; nt++) {
            int c0 = nt * 8 + tig * 2;
            float b0 = sm.b1s[c0], b1 = sm.b1s[c0 + 1];
            *(__half2*)&sm.As[q0][c0] =
                __floats2half2_rn(sspf(acc[nt][0] + b0), sspf(acc[nt][1] + b1));
            *(__half2*)&sm.As[q1][c0] =
                __floats2half2_rn(sspf(acc[nt][2] + b0), sspf(acc[nt][3] + b1));
            *(__half2*)&sm.As[q2][c0] =
                __floats2half2_rn(sspf(acc[8 + nt][0] + b0), sspf(acc[8 + nt][1] + b1));
            *(__half2*)&sm.As[q3][c0] =
                __floats2half2_rn(sspf(acc[8 + nt][2] + b0), sspf(acc[8 + nt][3] + b1));
        }
        __syncthreads();

        // fp16 h[src] gathers for this thread's 4 rows (fly during gemm2)
        int s0 = (q0 < rows) ? src[base + q0] : 0;
        int s1 = (q1 < rows) ? src[base + q1] : 0;
        int s2 = (q2 < rows) ? src[base + q2] : 0;
        int s3 = (q3 < rows) ? src[base + q3] : 0;
        const __half2* h0p = (const __half2*)(g_h + (size_t)s0 * DD);
        const __half2* h1p = (const __half2*)(g_h + (size_t)s1 * DD);
        const __half2* h2p = (const __half2*)(g_h + (size_t)s2 * DD);
        const __half2* h3p = (const __half2*)(g_h + (size_t)s3 * DD);
        __half2 hv0[8], hv1[8], hv2[8], hv3[8];
        #pragma unroll
        for (int nt = 0; nt < 8; nt++) {
            hv0[nt] = h0p[nt * 4 + tig];
            hv1[nt] = h1p[nt * 4 + tig];
            hv2[nt] = h2p[nt * 4 + tig];
            hv3[nt] = h3p[nt * 4 + tig];
        }

        // ---- GEMM2 ----
        #pragma unroll
        for (int i = 0; i < 16; i++)
            #pragma unroll
            for (int j = 0; j < 4; j++) acc[i][j] = 0.f;
        #pragma unroll
        for (int ks = 0; ks < 4; ks++) {
            int k0 = ks * 16 + tig * 2;
            unsigned a0 = *(const unsigned*)&sm.As[q0][k0];
            unsigned a1 = *(const unsigned*)&sm.As[q1][k0];
            unsigned a2 = *(const unsigned*)&sm.As[q0][k0 + 8];
            unsigned a3 = *(const unsigned*)&sm.As[q1][k0 + 8];
            unsigned a4 = *(const unsigned*)&sm.As[q2][k0];
            unsigned a5 = *(const unsigned*)&sm.As[q3][k0];
            unsigned a6 = *(const unsigned*)&sm.As[q2][k0 + 8];
            unsigned a7 = *(const unsigned*)&sm.As[q3][k0 + 8];
            #pragma unroll
            for (int nt = 0; nt < 8; nt++) {
                uint2 b = ((const uint2*)sm.Wp2)[(ks * 8 + nt) * 32 + lane];
                mma_f16(acc[nt],     a0, a1, a2, a3, b.x, b.y);
                mma_f16(acc[8 + nt], a4, a5, a6, a7, b.x, b.y);
            }
        }
        __syncthreads();  // all warps done reading As before staging msg in it

        // msg = ssp(x + b2) * h -> fp16 staging (reuse As, stride 72)
        #pragma unroll
        for (int nt = 0; nt < 8; nt++) {
            int c0 = nt * 8 + tig * 2;
            float b0 = sm.b2s[c0], b1 = sm.b2s[c0 + 1];
            float2 f0 = __half22float2(hv0[nt]);
            float2 f1 = __half22float2(hv1[nt]);
            float2 f2 = __half22float2(hv2[nt]);
            float2 f3 = __half22float2(hv3[nt]);
            *(__half2*)&sm.As[q0][c0] = __floats2half2_rn(
                sspf(acc[nt][0] + b0) * f0.x, sspf(acc[nt][1] + b1) * f0.y);
            *(__half2*)&sm.As[q1][c0] = __floats2half2_rn(
                sspf(acc[nt][2] + b0) * f1.x, sspf(acc[nt][3] + b1) * f1.y);
            *(__half2*)&sm.As[q2][c0] = __floats2half2_rn(
                sspf(acc[8 + nt][0] + b0) * f2.x, sspf(acc[8 + nt][1] + b1) * f2.y);
            *(__half2*)&sm.As[q3][c0] = __floats2half2_rn(
                sspf(acc[8 + nt][2] + b0) * f3.x, sspf(acc[8 + nt][3] + b1) * f3.y);
        }
        __syncthreads();

        // scatter 128B rows to CSR slots (2 passes, 64B per thread)
        #pragma unroll
        for (int p = 0; p < 2; p++) {
            int r = (tid >> 1) + p * 128, part = tid & 1;
            if (r < rows) {
                int slot = sm.slotS[r];
                const uint4* sp = (const uint4*)&sm.As[r][part * 32];
                uint4* dp = (uint4*)(g_msg + (size_t)slot * DD + part * 32);
                #pragma unroll
                for (int i = 0; i < 4; i++) dp[i] = sp[i];
            }
        }
    }
}

// ---------------- node kernel: 4-rows/iter segment-sum + fused MLP ----------
struct NodeSmem {
    float Wc[64][64];
    float Wo[64][64];
    float agg[16][64];
    float bcs[64], bos[64];
};
__global__ void __launch_bounds__(512, 2)
node_kernel(const float* __restrict__ Wc, const float* __restrict__ bc,
            const float* __restrict__ Wo, const float* __restrict__ bo,
            float* __restrict__ out) {
    extern __shared__ char smraw[];
    NodeSmem& sm = *reinterpret_cast<NodeSmem*>(smraw);
    int tid = threadIdx.x, lane = tid & 31, warp = tid >> 5;  // 16 warps
    for (int i = tid; i < 4096; i += 512) ((float*)sm.Wc)[i] = Wc[i];
    for (int i = tid; i < 4096; i += 512) ((float*)sm.Wo)[i] = Wo[i];
    if (tid < 64) { sm.bcs[tid] = bc[tid]; sm.bos[tid] = bo[tid]; }
    __syncthreads();

    int v = blockIdx.x * 16 + warp;  // NV = 3125*16 exactly
    int s0 = g_off[v], s1 = g_off[v + 1];
    // lane reads uint4 (8 halves) covering 4 rows per iteration:
    //   row = s + (lane>>3), cols (lane&7)*8 .. +7
    const int rsel = lane >> 3, c8 = (lane & 7) * 8;
    float a[8];
    #pragma unroll
    for (int i = 0; i < 8; i++) a[i] = 0.f;
    #pragma unroll 2
    for (int s = s0; s < s1; s += 4) {
        int row = s + rsel;
        if (row < s1) {
            uint4 u = *(const uint4*)(g_msg + (size_t)row * DD + c8);
            float2 f0 = __half22float2(*(__half2*)&u.x);
            float2 f1 = __half22float2(*(__half2*)&u.y);
            float2 f2 = __half22float2(*(__half2*)&u.z);
            float2 f3 = __half22float2(*(__half2*)&u.w);
            a[0] += f0.x; a[1] += f0.y; a[2] += f1.x; a[3] += f1.y;
            a[4] += f2.x; a[5] += f2.y; a[6] += f3.x; a[7] += f3.y;
        }
    }
    // combine the four row-groups (lanes with same lane&7 hold same cols)
    #pragma unroll
    for (int i = 0; i < 8; i++) {
        a[i] += __shfl_xor_sync(0xffffffffu, a[i], 8);
        a[i] += __shfl_xor_sync(0xffffffffu, a[i], 16);
    }
    if (lane < 8) {
        *(float4*)&sm.agg[warp][c8]     = make_float4(a[0], a[1], a[2], a[3]);
        *(float4*)&sm.agg[warp][c8 + 4] = make_float4(a[4], a[5], a[6], a[7]);
    }
    __syncwarp();

    float o0 = sm.bcs[2 * lane], o1 = sm.bcs[2 * lane + 1];
    #pragma unroll 8
    for (int k = 0; k < 64; k++) {
        float av = sm.agg[warp][k];
        float2 w = *(const float2*)&sm.Wc[k][2 * lane];
        o0 += av * w.x;
        o1 += av * w.y;
    }
    o0 = sspf(o0);
    o1 = sspf(o1);
    __syncwarp();
    sm.agg[warp][2 * lane]     = o0;
    sm.agg[warp][2 * lane + 1] = o1;
    __syncwarp();

    float r0 = sm.bos[2 * lane], r1 = sm.bos[2 * lane + 1];
    #pragma unroll 8
    for (int k = 0; k < 64; k++) {
        float tv = sm.agg[warp][k];
        float2 w = *(const float2*)&sm.Wo[k][2 * lane];
        r0 += tv * w.x;
        r1 += tv * w.y;
    }
    *(float2*)(out + (size_t)v * DD + 2 * lane) = make_float2(r0, r1);
}

// ---------------- launch ----------------------------------------------------
extern "C" void kernel_launch(void* const* d_in, const int* in_sizes, int n_in,
                              void* d_out, int out_size) {
    const float* nf  = (const float*)d_in[0];
    const float* ef  = (const float*)d_in[1];
    const int*   src = (const int*)d_in[2];
    const int*   dst = (const int*)d_in[3];
    const float* We1 = (const float*)d_in[4];
    const float* be1 = (const float*)d_in[5];
    const float* We2 = (const float*)d_in[6];
    const float* be2 = (const float*)d_in[7];
    const float* Wn  = (const float*)d_in[8];
    const float* bn  = (const float*)d_in[9];
    const float* Wc  = (const float*)d_in[10];
    const float* bc  = (const float*)d_in[11];
    const float* Wo  = (const float*)d_in[12];
    const float* bo  = (const float*)d_in[13];
    float* out = (float*)d_out;

    cudaFuncSetAttribute(edge_kernel, cudaFuncAttributeMaxDynamicSharedMemorySize,
                         (int)sizeof(EdgeSmem));
    cudaFuncSetAttribute(h_kernel, cudaFuncAttributeMaxDynamicSharedMemorySize,
                         (int)sizeof(HSmem));
    cudaFuncSetAttribute(node_kernel, cudaFuncAttributeMaxDynamicSharedMemorySize,
                         (int)sizeof(NodeSmem));

    const int scanBlocks = (NV + 1023) / 1024;  // 49
    // g_cnt is zero on entry (.bss on call 1; scan1 clears it for later replays)
    hist_kernel<<<(NE + 255) / 256, 256>>>(dst);
    scan1_kernel<<<scanBlocks, 1024>>>();
    scan2_kernel<<<1, 1>>>();
    scan3_kernel<<<scanBlocks, 1024>>>();
    h_kernel<<<(NV + 127) / 128, 256, sizeof(HSmem)>>>(nf, Wn, bn);
    edge_kernel<<<592, 256, sizeof(EdgeSmem)>>>(ef, src, dst, We1, be1, We2, be2);
    node_kernel<<<NV / 16, 512, sizeof(NodeSmem)>>>(Wc, bc, Wo, bo, out);
}